// round 7
// baseline (speedup 1.0000x reference)
#include <cuda_runtime.h>
#include <cstdint>

// Problem constants
#define B_   4
#define S_   1024
#define D_   1024
#define H_   16
#define HD_  64
#define QKVN 3072
#define M_   (B_ * S_)

// Scratch (static device globals — allocation-free per harness rules)
__device__ float g_qkv[(size_t)M_ * QKVN];   // [b,s, h*192 + {q,k,v}*64]
__device__ float g_ctx[(size_t)M_ * D_];     // [b,s, h*64+d]

// ---------------------------------------------------------------------------
// helpers
// ---------------------------------------------------------------------------
__device__ __forceinline__ float to_tf32(float x) {
    uint32_t u;
    asm("cvt.rna.tf32.f32 %0, %1;" : "=r"(u) : "f"(x));
    return __uint_as_float(u);
}

__device__ __forceinline__ void mma_tf32(float* d, const uint32_t* a, const uint32_t* b) {
    asm volatile(
        "mma.sync.aligned.m16n8k8.row.col.f32.tf32.tf32.f32 "
        "{%0,%1,%2,%3}, {%4,%5,%6,%7}, {%8,%9}, {%0,%1,%2,%3};\n"
        : "+f"(d[0]), "+f"(d[1]), "+f"(d[2]), "+f"(d[3])
        : "r"(a[0]), "r"(a[1]), "r"(a[2]), "r"(a[3]), "r"(b[0]), "r"(b[1]));
}

// ---------------------------------------------------------------------------
// tf32 GEMM: block tile 128x128, BK=32, 8 warps (2 M x 4 N), warp tile 64x32.
// 2 CTAs/SM (launch_bounds 256,2) for issue parallelism.
// As stride 36 (CF: bank 4g+a), Bs stride 136 (CF: 8a+g).
// ---------------------------------------------------------------------------
#define BK   32
#define ASTR 36
#define BSTR 136
#define BM_T 128
#define ATILE (BM_T * ASTR)
#define BTILE (BK * BSTR)
#define GEMM_SMEM (2 * (ATILE + BTILE) * 4)

__device__ __forceinline__ void gemm_tf32_body(
    const float* __restrict__ A, const float* __restrict__ Bm,
    const float* __restrict__ bias, float* __restrict__ C,
    int N, int K)
{
    extern __shared__ float smg[];
    float* As = smg;              // [2][ATILE]
    float* Bs = smg + 2 * ATILE;  // [2][BTILE]

    const int tid  = threadIdx.x;
    const int lane = tid & 31;
    const int wid  = tid >> 5;
    const int wm   = (wid & 1) * 64;    // warp M offset (0,64)
    const int wn   = (wid >> 1) * 32;   // warp N offset (0,32,64,96)
    const int bx   = blockIdx.x * 128;
    const int by   = blockIdx.y * BM_T;

    const int g = lane >> 2;
    const int a = lane & 3;

    float acc[4][4][4];
#pragma unroll
    for (int i = 0; i < 4; i++)
#pragma unroll
        for (int j = 0; j < 4; j++)
#pragma unroll
            for (int v = 0; v < 4; v++) acc[i][j][v] = 0.f;

    const int arow0 = tid >> 3;          // 0..31 (+32*i, 4 iters)
    const int acol  = (tid & 7) * 4;
    const int brow0 = tid >> 5;          // 0..7 (+8*i, 4 iters)
    const int bcol  = (tid & 31) * 4;

    float4 av[4], bv[4];

#define G_LOAD(k0)                                                              \
    {                                                                           \
        _Pragma("unroll")                                                       \
        for (int i = 0; i < 4; i++)                                             \
            av[i] = *(const float4*)(A + (size_t)(by + arow0 + 32 * i) * K + (k0) + acol); \
        _Pragma("unroll")                                                       \
        for (int i = 0; i < 4; i++)                                             \
            bv[i] = *(const float4*)(Bm + (size_t)((k0) + brow0 + 8 * i) * N + bx + bcol); \
    }

#define G_STORE(buf)                                                            \
    {                                                                           \
        float* Ad = As + (buf) * ATILE;                                         \
        float* Bd = Bs + (buf) * BTILE;                                         \
        _Pragma("unroll")                                                       \
        for (int i = 0; i < 4; i++) {                                           \
            float4 t = av[i];                                                   \
            t.x = to_tf32(t.x); t.y = to_tf32(t.y);                             \
            t.z = to_tf32(t.z); t.w = to_tf32(t.w);                             \
            *(float4*)(Ad + (arow0 + 32 * i) * ASTR + acol) = t;                \
        }                                                                       \
        _Pragma("unroll")                                                       \
        for (int i = 0; i < 4; i++) {                                           \
            float4 t = bv[i];                                                   \
            t.x = to_tf32(t.x); t.y = to_tf32(t.y);                             \
            t.z = to_tf32(t.z); t.w = to_tf32(t.w);                             \
            *(float4*)(Bd + (brow0 + 8 * i) * BSTR + bcol) = t;                 \
        }                                                                       \
    }

    const int nk = K / BK;
    G_LOAD(0);
    G_STORE(0);
    G_LOAD(BK);
    __syncthreads();

    for (int it = 0; it < nk; it++) {
        const float* Ab_ = As + (it & 1) * ATILE;
        const float* Bb_ = Bs + (it & 1) * BTILE;
        if (it + 1 < nk) G_STORE((it + 1) & 1);
        if (it + 2 < nk) G_LOAD((it + 2) * BK);

#pragma unroll
        for (int kk = 0; kk < BK; kk += 8) {
            uint32_t af[4][4], bf[4][2];
#pragma unroll
            for (int i = 0; i < 4; i++) {
                int r = wm + i * 16 + g;
                af[i][0] = __float_as_uint(Ab_[(r)     * ASTR + kk + a]);
                af[i][1] = __float_as_uint(Ab_[(r + 8) * ASTR + kk + a]);
                af[i][2] = __float_as_uint(Ab_[(r)     * ASTR + kk + 4 + a]);
                af[i][3] = __float_as_uint(Ab_[(r + 8) * ASTR + kk + 4 + a]);
            }
#pragma unroll
            for (int j = 0; j < 4; j++) {
                int n = wn + j * 8 + g;
                bf[j][0] = __float_as_uint(Bb_[(kk + a)     * BSTR + n]);
                bf[j][1] = __float_as_uint(Bb_[(kk + 4 + a) * BSTR + n]);
            }
#pragma unroll
            for (int i = 0; i < 4; i++)
#pragma unroll
                for (int j = 0; j < 4; j++)
                    mma_tf32(acc[i][j], af[i], bf[j]);
        }
        __syncthreads();
    }
#undef G_LOAD
#undef G_STORE

#pragma unroll
    for (int i = 0; i < 4; i++) {
        int row = by + wm + i * 16 + g;
#pragma unroll
        for (int j = 0; j < 4; j++) {
            int col = bx + wn + j * 8 + a * 2;
            float b0 = bias[col], b1 = bias[col + 1];
            *(float2*)(C + (size_t)row * N + col) =
                make_float2(acc[i][j][0] + b0, acc[i][j][1] + b1);
            *(float2*)(C + (size_t)(row + 8) * N + col) =
                make_float2(acc[i][j][2] + b0, acc[i][j][3] + b1);
        }
    }
}

__global__ __launch_bounds__(256, 2) void qkv_gemm_kernel(
    const float* __restrict__ x, const float* __restrict__ W,
    const float* __restrict__ bias)
{
    gemm_tf32_body(x, W, bias, g_qkv, QKVN, D_);
}

__global__ __launch_bounds__(256, 2) void out_gemm_kernel(
    const float* __restrict__ W, const float* __restrict__ bias,
    float* __restrict__ out)
{
    gemm_tf32_body(g_ctx, W, bias, out, D_, D_);
}

// ---------------------------------------------------------------------------
// Fused attention, QT=32, 512 threads (16 warps).
// K tiles at stride 68 (CF bank 4g+a for score B-frags), V tiles at stride 72
// (CF bank 8a+g for ctx B-frags). sc stays fp32; ctx converts in registers.
// att global write interleaved into ctx chunks (hidden under MMA).
// ---------------------------------------------------------------------------
#define QT     32
#define KVT    128
#define SCSTR  1028
#define QSTR   68
#define KSTR   68
#define VSTR   72
#define KVTILE (KVT * VSTR)     // max of the two layouts
#define NTHR   512
#define RSTR   68
#define ATTN_SMEM ((QT * SCSTR + QT * QSTR + 2 * KVTILE) * 4)

__global__ __launch_bounds__(NTHR) void attn_kernel(
    const float* __restrict__ mask, float* __restrict__ att)
{
    extern __shared__ float sm[];
    float* sc = sm;                      // [QT][SCSTR]
    float* qs = sc + QT * SCSTR;         // [QT][QSTR]
    float* kv = qs + QT * QSTR;          // [2][KVTILE]

    const int b    = blockIdx.z;
    const int h    = blockIdx.y;
    const int q0   = blockIdx.x * QT;
    const int tid  = threadIdx.x;
    const int lane = tid & 31;
    const int w    = tid >> 5;
    const int g = lane >> 2;
    const int a = lane & 3;
    const int rbase = (w >> 3) * 16;     // 0 or 16
    const int cg    = (w & 7);           // 0..7

    const int ldrow = tid >> 4;          // 0..31 (+32*i)
    const int ldcol = (tid & 15) * 4;

    const float* qkv_b = g_qkv + (size_t)(b * S_) * QKVN + h * 192;
    float* abase = att + ((size_t)(b * H_ + h) * S_ + q0) * S_;

    float4 pf[4];
    float2 mreg[2][2], mnext[2][2];

#define KV_LDG(off, c)                                                         \
    {                                                                          \
        _Pragma("unroll")                                                      \
        for (int i = 0; i < 4; i++)                                            \
            pf[i] = *(const float4*)(qkv_b +                                   \
                (size_t)((c) * KVT + ldrow + 32 * i) * QKVN + (off) + ldcol);  \
    }
#define KV_STS(buf, str)                                                       \
    {                                                                          \
        float* dst = kv + (buf) * KVTILE;                                      \
        _Pragma("unroll")                                                      \
        for (int i = 0; i < 4; i++) {                                          \
            float4 t = pf[i];                                                  \
            t.x = to_tf32(t.x); t.y = to_tf32(t.y);                            \
            t.z = to_tf32(t.z); t.w = to_tf32(t.w);                            \
            *(float4*)(dst + (ldrow + 32 * i) * (str) + ldcol) = t;            \
        }                                                                      \
    }
#define MASK_LDG(dst, c)                                                       \
    {                                                                          \
        const float* mp = mask + ((size_t)(b * S_) + (q0 + rbase + g)) * S_    \
                          + (c) * 128 + cg * 16 + a * 2;                       \
        dst[0][0] = *(const float2*)(mp);                                      \
        dst[0][1] = *(const float2*)(mp + 8);                                  \
        mp += (size_t)8 * S_;                                                  \
        dst[1][0] = *(const float2*)(mp);                                      \
        dst[1][1] = *(const float2*)(mp + 8);                                  \
    }

    // ---- prologue: Q tile, K chunk 0, mask chunk 0 ----
    for (int idx = tid; idx < QT * HD_; idx += NTHR) {
        int qi = idx >> 6, d = idx & 63;
        qs[qi * QSTR + d] = to_tf32(qkv_b[(size_t)(q0 + qi) * QKVN + d] * 0.125f);
    }
    KV_LDG(64, 0);
    KV_STS(0, KSTR);
    KV_LDG(64, 1);
    MASK_LDG(mreg, 0);
    __syncthreads();

    // hoist Q fragments (invariant over chunks)
    uint32_t afq[8][4];
#pragma unroll
    for (int ks = 0; ks < 8; ks++) {
        int k0 = ks * 8;
        afq[ks][0] = __float_as_uint(qs[(rbase + g)     * QSTR + k0 + a]);
        afq[ks][1] = __float_as_uint(qs[(rbase + g + 8) * QSTR + k0 + a]);
        afq[ks][2] = __float_as_uint(qs[(rbase + g)     * QSTR + k0 + 4 + a]);
        afq[ks][3] = __float_as_uint(qs[(rbase + g + 8) * QSTR + k0 + 4 + a]);
    }

    // ---- scores: 1 sync per chunk ----
    for (int c = 0; c < 8; c++) {
        const float* kvc = kv + (c & 1) * KVTILE;
        if (c < 7) KV_STS((c + 1) & 1, KSTR);
        if (c < 6) KV_LDG(64, c + 2);
        if (c < 7) MASK_LDG(mnext, c + 1);

        float acc2[2][4] = {{0.f,0.f,0.f,0.f},{0.f,0.f,0.f,0.f}};
#pragma unroll
        for (int ks = 0; ks < 8; ks++) {
            int k0 = ks * 8;
            uint32_t bf[2][2];
#pragma unroll
            for (int j = 0; j < 2; j++) {
                int n = cg * 16 + j * 8 + g;
                bf[j][0] = __float_as_uint(kvc[n * KSTR + k0 + a]);
                bf[j][1] = __float_as_uint(kvc[n * KSTR + k0 + 4 + a]);
            }
            mma_tf32(acc2[0], afq[ks], bf[0]);
            mma_tf32(acc2[1], afq[ks], bf[1]);
        }
#pragma unroll
        for (int j = 0; j < 2; j++) {
            int colG = c * 128 + cg * 16 + j * 8 + a * 2;
            sc[(rbase + g)     * SCSTR + colG]     = acc2[j][0] + mreg[0][j].x;
            sc[(rbase + g)     * SCSTR + colG + 1] = acc2[j][1] + mreg[0][j].y;
            sc[(rbase + g + 8) * SCSTR + colG]     = acc2[j][2] + mreg[1][j].x;
            sc[(rbase + g + 8) * SCSTR + colG + 1] = acc2[j][3] + mreg[1][j].y;
        }
#pragma unroll
        for (int i = 0; i < 2; i++)
#pragma unroll
            for (int j = 0; j < 2; j++) mreg[i][j] = mnext[i][j];
        __syncthreads();
    }

    // prefetch V chunk 0 (overlaps softmax)
    KV_LDG(128, 0);

    // ---- softmax: one warp per 2 rows ----
    for (int r = w; r < QT; r += 16) {
        float* row = sc + r * SCSTR;
        float m = -1e30f;
        for (int k = lane; k < S_; k += 32) m = fmaxf(m, row[k]);
#pragma unroll
        for (int o = 16; o; o >>= 1) m = fmaxf(m, __shfl_xor_sync(~0u, m, o));
        float sum = 0.f;
        for (int k = lane; k < S_; k += 32) {
            float e = __expf(row[k] - m);
            row[k] = e;
            sum += e;
        }
#pragma unroll
        for (int o = 16; o; o >>= 1) sum += __shfl_xor_sync(~0u, sum, o);
        float inv = 1.f / sum;
        for (int k = lane; k < S_; k += 32) row[k] *= inv;
    }
    KV_STS(0, VSTR);    // stage V[0]
    KV_LDG(128, 1);
    __syncthreads();    // sc(softmaxed) + kv[0](V) visible

    // ---- ctx = P @ V, att write interleaved per chunk ----
    float acc3[8][4];
#pragma unroll
    for (int j = 0; j < 8; j++)
#pragma unroll
        for (int v = 0; v < 4; v++) acc3[j][v] = 0.f;

    for (int c = 0; c < 8; c++) {
        const float* kvc = kv + (c & 1) * KVTILE;
        if (c < 7) KV_STS((c + 1) & 1, VSTR);
        if (c < 6) KV_LDG(128, c + 2);

        // att write for this chunk's columns (hidden under MMAs)
        {
            int row0 = tid >> 5;          // 0..15
            int c4   = tid & 31;          // float4 index within chunk row
            int col  = c * 128 + c4 * 4;
            *(float4*)(abase + (size_t)row0 * S_ + col) =
                *(const float4*)(sc + row0 * SCSTR + col);
            *(float4*)(abase + (size_t)(row0 + 16) * S_ + col) =
                *(const float4*)(sc + (row0 + 16) * SCSTR + col);
        }

#pragma unroll
        for (int s = 0; s < 2; s++) {
            int kl = cg * 16 + s * 8;        // chunk-local k offset
            int kg = c * 128 + kl;           // global
            uint32_t af[4];
            af[0] = __float_as_uint(to_tf32(sc[(rbase + g)     * SCSTR + kg + a]));
            af[1] = __float_as_uint(to_tf32(sc[(rbase + g + 8) * SCSTR + kg + a]));
            af[2] = __float_as_uint(to_tf32(sc[(rbase + g)     * SCSTR + kg + 4 + a]));
            af[3] = __float_as_uint(to_tf32(sc[(rbase + g + 8) * SCSTR + kg + 4 + a]));
#pragma unroll
            for (int j = 0; j < 8; j++) {
                uint32_t bf[2];
                bf[0] = __float_as_uint(kvc[(kl + a)     * VSTR + j * 8 + g]);
                bf[1] = __float_as_uint(kvc[(kl + 4 + a) * VSTR + j * 8 + g]);
                mma_tf32(acc3[j], af, bf);
            }
        }
        __syncthreads();
    }
#undef KV_LDG
#undef KV_STS
#undef MASK_LDG

    // ---- cross-warp reduction over the 8 k-slice warps (staged in sc) ----
    {
        float* red = sc;
#pragma unroll
        for (int j = 0; j < 8; j++) {
            *(float2*)(red + (w * 16 + g)     * RSTR + j * 8 + a * 2) =
                make_float2(acc3[j][0], acc3[j][1]);
            *(float2*)(red + (w * 16 + g + 8) * RSTR + j * 8 + a * 2) =
                make_float2(acc3[j][2], acc3[j][3]);
        }
        __syncthreads();

        int rg  = tid >> 8;            // 0..1
        int row = (tid >> 4) & 15;     // 0..15
        int d4  = (tid & 15) * 4;      // 0..60
        float4 s = make_float4(0.f, 0.f, 0.f, 0.f);
#pragma unroll
        for (int k = 0; k < 8; k++) {
            const float* p = red + ((rg * 8 + k) * 16 + row) * RSTR + d4;
            s.x += p[0]; s.y += p[1]; s.z += p[2]; s.w += p[3];
        }
        int rowg = b * S_ + q0 + rg * 16 + row;
        *(float4*)(g_ctx + (size_t)rowg * D_ + h * HD_ + d4) = s;
    }
}

// ---------------------------------------------------------------------------
extern "C" void kernel_launch(void* const* d_in, const int* in_sizes, int n_in,
                              void* d_out, int out_size)
{
    const float* x    = (const float*)d_in[0];
    const float* mask = (const float*)d_in[1];
    const float* Wqkv = (const float*)d_in[2];
    const float* bqkv = (const float*)d_in[3];
    const float* Wo   = (const float*)d_in[4];
    const float* bo   = (const float*)d_in[5];

    float* out = (float*)d_out;                       // [B,S,D]
    float* att = out + (size_t)B_ * S_ * D_;          // [B,H,S,S]

    cudaFuncSetAttribute(attn_kernel,
                         cudaFuncAttributeMaxDynamicSharedMemorySize, ATTN_SMEM);
    cudaFuncSetAttribute(qkv_gemm_kernel,
                         cudaFuncAttributeMaxDynamicSharedMemorySize, GEMM_SMEM);
    cudaFuncSetAttribute(out_gemm_kernel,
                         cudaFuncAttributeMaxDynamicSharedMemorySize, GEMM_SMEM);

    // 1) fused QKV projection (tf32 tensor cores)
    {
        dim3 grid(QKVN / 128, M_ / BM_T);
        qkv_gemm_kernel<<<grid, 256, GEMM_SMEM>>>(x, Wqkv, bqkv);
    }
    // 2) fused attention (scores + softmax + att write + ctx)
    {
        dim3 grid(S_ / QT, H_, B_);
        attn_kernel<<<grid, NTHR, ATTN_SMEM>>>(mask, att);
    }
    // 3) output projection
    {
        dim3 grid(D_ / 128, M_ / BM_T);
        out_gemm_kernel<<<grid, 256, GEMM_SMEM>>>(Wo, bo, out);
    }
}

// round 8
// speedup vs baseline: 1.7408x; 1.7408x over previous
#include <cuda_runtime.h>
#include <cstdint>

// Problem constants
#define B_   4
#define S_   1024
#define D_   1024
#define H_   16
#define HD_  64
#define QKVN 3072
#define M_   (B_ * S_)

// Scratch (static device globals — allocation-free per harness rules)
__device__ float g_qkv[(size_t)M_ * QKVN];   // [b,s, h*192 + {q,k,v}*64]
__device__ float g_ctx[(size_t)M_ * D_];     // [b,s, h*64+d]

// ---------------------------------------------------------------------------
// helpers
// ---------------------------------------------------------------------------
__device__ __forceinline__ float to_tf32(float x) {
    uint32_t u;
    asm("cvt.rna.tf32.f32 %0, %1;" : "=r"(u) : "f"(x));
    return __uint_as_float(u);
}

__device__ __forceinline__ void mma_tf32(float* d, const uint32_t* a, const uint32_t* b) {
    asm volatile(
        "mma.sync.aligned.m16n8k8.row.col.f32.tf32.tf32.f32 "
        "{%0,%1,%2,%3}, {%4,%5,%6,%7}, {%8,%9}, {%0,%1,%2,%3};\n"
        : "+f"(d[0]), "+f"(d[1]), "+f"(d[2]), "+f"(d[3])
        : "r"(a[0]), "r"(a[1]), "r"(a[2]), "r"(a[3]), "r"(b[0]), "r"(b[1]));
}

// ---------------------------------------------------------------------------
// tf32 GEMM (proven R3/R4 form): 128x128 tile, BK=32, 8 warps (4M x 2N),
// warp tile 32x64, static smem, single buffer.
// ---------------------------------------------------------------------------
#define BK   32
#define ASTR 36
#define BSTR 136

__device__ __forceinline__ void gemm_tf32_body(
    const float* __restrict__ A, const float* __restrict__ Bm,
    const float* __restrict__ bias, float* __restrict__ C,
    int N, int K)
{
    __shared__ float As[128 * ASTR];
    __shared__ float Bs[BK * BSTR];

    const int tid  = threadIdx.x;
    const int lane = tid & 31;
    const int wid  = tid >> 5;
    const int wm   = (wid & 3) * 32;
    const int wn   = (wid >> 2) * 64;
    const int bx   = blockIdx.x * 128;
    const int by   = blockIdx.y * 128;

    const int g = lane >> 2;
    const int a = lane & 3;

    float acc[2][8][4];
#pragma unroll
    for (int i = 0; i < 2; i++)
#pragma unroll
        for (int j = 0; j < 8; j++)
#pragma unroll
            for (int v = 0; v < 4; v++) acc[i][j][v] = 0.f;

    const int arow0 = tid >> 3;
    const int acol  = (tid & 7) * 4;
    const int brow0 = tid >> 5;
    const int bcol  = (tid & 31) * 4;

    for (int k0 = 0; k0 < K; k0 += BK) {
        float4 av[4], bv[4];
#pragma unroll
        for (int i = 0; i < 4; i++)
            av[i] = *(const float4*)(A + (size_t)(by + arow0 + 32 * i) * K + k0 + acol);
#pragma unroll
        for (int i = 0; i < 4; i++)
            bv[i] = *(const float4*)(Bm + (size_t)(k0 + brow0 + 8 * i) * N + bx + bcol);

        __syncthreads();
#pragma unroll
        for (int i = 0; i < 4; i++) {
            float4 t = av[i];
            t.x = to_tf32(t.x); t.y = to_tf32(t.y); t.z = to_tf32(t.z); t.w = to_tf32(t.w);
            *(float4*)(As + (arow0 + 32 * i) * ASTR + acol) = t;
        }
#pragma unroll
        for (int i = 0; i < 4; i++) {
            float4 t = bv[i];
            t.x = to_tf32(t.x); t.y = to_tf32(t.y); t.z = to_tf32(t.z); t.w = to_tf32(t.w);
            *(float4*)(Bs + (brow0 + 8 * i) * BSTR + bcol) = t;
        }
        __syncthreads();

#pragma unroll
        for (int kk = 0; kk < BK; kk += 8) {
            uint32_t af[2][4], bf[8][2];
#pragma unroll
            for (int i = 0; i < 2; i++) {
                int r = wm + i * 16 + g;
                af[i][0] = __float_as_uint(As[(r)     * ASTR + kk + a]);
                af[i][1] = __float_as_uint(As[(r + 8) * ASTR + kk + a]);
                af[i][2] = __float_as_uint(As[(r)     * ASTR + kk + 4 + a]);
                af[i][3] = __float_as_uint(As[(r + 8) * ASTR + kk + 4 + a]);
            }
#pragma unroll
            for (int j = 0; j < 8; j++) {
                int n = wn + j * 8 + g;
                bf[j][0] = __float_as_uint(Bs[(kk + a)     * BSTR + n]);
                bf[j][1] = __float_as_uint(Bs[(kk + 4 + a) * BSTR + n]);
            }
#pragma unroll
            for (int i = 0; i < 2; i++)
#pragma unroll
                for (int j = 0; j < 8; j++)
                    mma_tf32(acc[i][j], af[i], bf[j]);
        }
    }

#pragma unroll
    for (int i = 0; i < 2; i++) {
        int row = by + wm + i * 16 + g;
#pragma unroll
        for (int j = 0; j < 8; j++) {
            int col = bx + wn + j * 8 + a * 2;
            float b0 = bias[col], b1 = bias[col + 1];
            *(float2*)(C + (size_t)row * N + col) =
                make_float2(acc[i][j][0] + b0, acc[i][j][1] + b1);
            *(float2*)(C + (size_t)(row + 8) * N + col) =
                make_float2(acc[i][j][2] + b0, acc[i][j][3] + b1);
        }
    }
}

__global__ __launch_bounds__(256) void qkv_gemm_kernel(
    const float* __restrict__ x, const float* __restrict__ W,
    const float* __restrict__ bias)
{
    gemm_tf32_body(x, W, bias, g_qkv, QKVN, D_);
}

__global__ __launch_bounds__(256) void out_gemm_kernel(
    const float* __restrict__ W, const float* __restrict__ bias,
    float* __restrict__ out)
{
    gemm_tf32_body(g_ctx, W, bias, out, D_, D_);
}

// ---------------------------------------------------------------------------
// scores kernel: att_raw[b,h,q,k] = (Q*0.125) @ K^T + mask[b,q,k]
// per block: 128q x 128k tile of one (b,h). K(dim)=64, one-shot tiles.
// 8 warps (4M x 2N), warp tile 32x64. Qs/Ks stride 68 (CF: 4g+a).
// ---------------------------------------------------------------------------
#define SC_STR 68
#define SCORES_SMEM ((128 * SC_STR * 2) * 4)

__global__ __launch_bounds__(256) void scores_kernel(
    const float* __restrict__ mask, float* __restrict__ att)
{
    extern __shared__ float sms[];
    float* Qs = sms;                 // [128][68]
    float* Ks = sms + 128 * SC_STR;  // [128][68]

    const int bh = blockIdx.z;
    const int b  = bh >> 4, h = bh & 15;
    const int qt = blockIdx.y * 128;
    const int kt = blockIdx.x * 128;
    const int tid = threadIdx.x;
    const int lane = tid & 31, w = tid >> 5;
    const int g = lane >> 2, a = lane & 3;
    const int wm = (w & 3) * 32, wn = (w >> 2) * 64;

    const float* qkv_b = g_qkv + (size_t)(b * S_) * QKVN + h * 192;

    // load Q & K tiles (tf32; Q pre-scaled)
    {
        int row = tid >> 4;            // 0..15 (+16*i)
        int c4  = (tid & 15) * 4;
#pragma unroll
        for (int i = 0; i < 8; i++) {
            float4 t = *(const float4*)(qkv_b + (size_t)(qt + row + 16 * i) * QKVN + c4);
            t.x = to_tf32(t.x * 0.125f); t.y = to_tf32(t.y * 0.125f);
            t.z = to_tf32(t.z * 0.125f); t.w = to_tf32(t.w * 0.125f);
            *(float4*)(Qs + (row + 16 * i) * SC_STR + c4) = t;
        }
#pragma unroll
        for (int i = 0; i < 8; i++) {
            float4 t = *(const float4*)(qkv_b + (size_t)(kt + row + 16 * i) * QKVN + 64 + c4);
            t.x = to_tf32(t.x); t.y = to_tf32(t.y); t.z = to_tf32(t.z); t.w = to_tf32(t.w);
            *(float4*)(Ks + (row + 16 * i) * SC_STR + c4) = t;
        }
    }
    __syncthreads();

    float acc[2][8][4];
#pragma unroll
    for (int i = 0; i < 2; i++)
#pragma unroll
        for (int j = 0; j < 8; j++)
#pragma unroll
            for (int v = 0; v < 4; v++) acc[i][j][v] = 0.f;

#pragma unroll
    for (int ks = 0; ks < 8; ks++) {
        int k0 = ks * 8;
        uint32_t af[2][4], bf[8][2];
#pragma unroll
        for (int i = 0; i < 2; i++) {
            int r = wm + i * 16 + g;
            af[i][0] = __float_as_uint(Qs[(r)     * SC_STR + k0 + a]);
            af[i][1] = __float_as_uint(Qs[(r + 8) * SC_STR + k0 + a]);
            af[i][2] = __float_as_uint(Qs[(r)     * SC_STR + k0 + 4 + a]);
            af[i][3] = __float_as_uint(Qs[(r + 8) * SC_STR + k0 + 4 + a]);
        }
#pragma unroll
        for (int j = 0; j < 8; j++) {
            int n = wn + j * 8 + g;
            bf[j][0] = __float_as_uint(Ks[n * SC_STR + k0 + a]);
            bf[j][1] = __float_as_uint(Ks[n * SC_STR + k0 + 4 + a]);
        }
#pragma unroll
        for (int i = 0; i < 2; i++)
#pragma unroll
            for (int j = 0; j < 8; j++)
                mma_tf32(acc[i][j], af[i], bf[j]);
    }

    // epilogue: + mask, write att
    float* abase = att + ((size_t)(b * H_ + h) * S_ + qt) * S_ + kt;
    const float* mbase = mask + ((size_t)(b * S_) + qt) * S_ + kt;
#pragma unroll
    for (int i = 0; i < 2; i++) {
        int r0 = wm + i * 16 + g;
#pragma unroll
        for (int j = 0; j < 8; j++) {
            int col = wn + j * 8 + a * 2;
            float2 m0 = *(const float2*)(mbase + (size_t)r0 * S_ + col);
            float2 m1 = *(const float2*)(mbase + (size_t)(r0 + 8) * S_ + col);
            *(float2*)(abase + (size_t)r0 * S_ + col) =
                make_float2(acc[i][j][0] + m0.x, acc[i][j][1] + m0.y);
            *(float2*)(abase + (size_t)(r0 + 8) * S_ + col) =
                make_float2(acc[i][j][2] + m1.x, acc[i][j][3] + m1.y);
        }
    }
}

// ---------------------------------------------------------------------------
// softmax kernel: in-place row softmax over att rows (length 1024).
// one warp per row, 8 rows per block.
// ---------------------------------------------------------------------------
__global__ __launch_bounds__(256) void softmax_kernel(float* __restrict__ att)
{
    const int lane = threadIdx.x & 31;
    const size_t row = (size_t)blockIdx.x * 8 + (threadIdx.x >> 5);
    float* p = att + row * S_;

    float4 v[8];
    float m = -1e30f;
#pragma unroll
    for (int i = 0; i < 8; i++) {
        v[i] = *(const float4*)(p + (i * 32 + lane) * 4);
        m = fmaxf(m, fmaxf(fmaxf(v[i].x, v[i].y), fmaxf(v[i].z, v[i].w)));
    }
#pragma unroll
    for (int o = 16; o; o >>= 1) m = fmaxf(m, __shfl_xor_sync(~0u, m, o));

    float sum = 0.f;
#pragma unroll
    for (int i = 0; i < 8; i++) {
        v[i].x = __expf(v[i].x - m); v[i].y = __expf(v[i].y - m);
        v[i].z = __expf(v[i].z - m); v[i].w = __expf(v[i].w - m);
        sum += v[i].x + v[i].y + v[i].z + v[i].w;
    }
#pragma unroll
    for (int o = 16; o; o >>= 1) sum += __shfl_xor_sync(~0u, sum, o);
    float inv = 1.f / sum;

#pragma unroll
    for (int i = 0; i < 8; i++) {
        v[i].x *= inv; v[i].y *= inv; v[i].z *= inv; v[i].w *= inv;
        *(float4*)(p + (i * 32 + lane) * 4) = v[i];
    }
}

// ---------------------------------------------------------------------------
// ctx kernel: g_ctx[b,s,h*64+d] = att[b,h,s,:] @ V[b,:,h,d]
// per block: 128 rows x 64 dims of one (b,h); K=1024 in BK=64 chunks,
// double-buffered. 8 warps (4M x 2N), warp tile 32x32.
// As stride 68 (CF 4g+a), Vs stride 72 (CF 8a+g).
// ---------------------------------------------------------------------------
#define CT_ASTR 68
#define CT_VSTR 72
#define CT_AT   (128 * CT_ASTR)
#define CT_VT   (64 * CT_VSTR)
#define CTX_SMEM (2 * (CT_AT + CT_VT) * 4)

__global__ __launch_bounds__(256) void ctx_kernel(const float* __restrict__ att)
{
    extern __shared__ float smc[];
    float* As = smc;                // [2][128][68]
    float* Vs = smc + 2 * CT_AT;    // [2][64][72]

    const int bh = blockIdx.y;
    const int b  = bh >> 4, h = bh & 15;
    const int mt = blockIdx.x * 128;
    const int tid = threadIdx.x;
    const int lane = tid & 31, w = tid >> 5;
    const int g = lane >> 2, a = lane & 3;
    const int wm = (w & 3) * 32, wn = (w >> 2) * 32;

    const float* abase = att + ((size_t)bh * S_ + mt) * S_;
    const float* vbase = g_qkv + (size_t)(b * S_) * QKVN + h * 192 + 128;

    const int lrow = tid >> 4;          // 0..15
    const int lc4  = (tid & 15) * 4;

    float4 avr[8], bvr[4];

#define A_LDG(c)                                                               \
    {                                                                          \
        _Pragma("unroll")                                                      \
        for (int i = 0; i < 8; i++)                                            \
            avr[i] = *(const float4*)(abase + (size_t)(lrow + 16 * i) * S_ +   \
                                      (c) * 64 + lc4);                         \
    }
#define A_STS(buf)                                                             \
    {                                                                          \
        float* dst = As + (buf) * CT_AT;                                       \
        _Pragma("unroll")                                                      \
        for (int i = 0; i < 8; i++) {                                          \
            float4 t = avr[i];                                                 \
            t.x = to_tf32(t.x); t.y = to_tf32(t.y);                            \
            t.z = to_tf32(t.z); t.w = to_tf32(t.w);                            \
            *(float4*)(dst + (lrow + 16 * i) * CT_ASTR + lc4) = t;             \
        }                                                                      \
    }
#define V_LDG(c)                                                               \
    {                                                                          \
        _Pragma("unroll")                                                      \
        for (int i = 0; i < 4; i++)                                            \
            bvr[i] = *(const float4*)(vbase +                                  \
                (size_t)((c) * 64 + lrow + 16 * i) * QKVN + lc4);              \
    }
#define V_STS(buf)                                                             \
    {                                                                          \
        float* dst = Vs + (buf) * CT_VT;                                       \
        _Pragma("unroll")                                                      \
        for (int i = 0; i < 4; i++) {                                          \
            float4 t = bvr[i];                                                 \
            t.x = to_tf32(t.x); t.y = to_tf32(t.y);                            \
            t.z = to_tf32(t.z); t.w = to_tf32(t.w);                            \
            *(float4*)(dst + (lrow + 16 * i) * CT_VSTR + lc4) = t;             \
        }                                                                      \
    }

    float acc[2][4][4];
#pragma unroll
    for (int i = 0; i < 2; i++)
#pragma unroll
        for (int j = 0; j < 4; j++)
#pragma unroll
            for (int v = 0; v < 4; v++) acc[i][j][v] = 0.f;

    const int nk = S_ / 64;   // 16 chunks
    A_LDG(0); A_STS(0);
    V_LDG(0); V_STS(0);
    A_LDG(1); V_LDG(1);
    __syncthreads();

    for (int c = 0; c < nk; c++) {
        const float* Ab_ = As + (c & 1) * CT_AT;
        const float* Vb_ = Vs + (c & 1) * CT_VT;
        if (c + 1 < nk) { A_STS((c + 1) & 1); V_STS((c + 1) & 1); }
        if (c + 2 < nk) { A_LDG(c + 2); V_LDG(c + 2); }

#pragma unroll
        for (int kk = 0; kk < 64; kk += 8) {
            uint32_t af[2][4], bf[4][2];
#pragma unroll
            for (int i = 0; i < 2; i++) {
                int r = wm + i * 16 + g;
                af[i][0] = __float_as_uint(Ab_[(r)     * CT_ASTR + kk + a]);
                af[i][1] = __float_as_uint(Ab_[(r + 8) * CT_ASTR + kk + a]);
                af[i][2] = __float_as_uint(Ab_[(r)     * CT_ASTR + kk + 4 + a]);
                af[i][3] = __float_as_uint(Ab_[(r + 8) * CT_ASTR + kk + 4 + a]);
            }
#pragma unroll
            for (int j = 0; j < 4; j++) {
                int n = wn + j * 8 + g;
                bf[j][0] = __float_as_uint(Vb_[(kk + a)     * CT_VSTR + n]);
                bf[j][1] = __float_as_uint(Vb_[(kk + 4 + a) * CT_VSTR + n]);
            }
#pragma unroll
            for (int i = 0; i < 2; i++)
#pragma unroll
                for (int j = 0; j < 4; j++)
                    mma_tf32(acc[i][j], af[i], bf[j]);
        }
        __syncthreads();
    }
#undef A_LDG
#undef A_STS
#undef V_LDG
#undef V_STS

#pragma unroll
    for (int i = 0; i < 2; i++) {
        int row = mt + wm + i * 16 + g;
#pragma unroll
        for (int j = 0; j < 4; j++) {
            int col = wn + j * 8 + a * 2;
            *(float2*)(g_ctx + (size_t)(b * S_ + row) * D_ + h * HD_ + col) =
                make_float2(acc[i][j][0], acc[i][j][1]);
            *(float2*)(g_ctx + (size_t)(b * S_ + row + 8) * D_ + h * HD_ + col) =
                make_float2(acc[i][j][2], acc[i][j][3]);
        }
    }
}

// ---------------------------------------------------------------------------
extern "C" void kernel_launch(void* const* d_in, const int* in_sizes, int n_in,
                              void* d_out, int out_size)
{
    const float* x    = (const float*)d_in[0];
    const float* mask = (const float*)d_in[1];
    const float* Wqkv = (const float*)d_in[2];
    const float* bqkv = (const float*)d_in[3];
    const float* Wo   = (const float*)d_in[4];
    const float* bo   = (const float*)d_in[5];

    float* out = (float*)d_out;                       // [B,S,D]
    float* att = out + (size_t)B_ * S_ * D_;          // [B,H,S,S]

    cudaFuncSetAttribute(scores_kernel,
                         cudaFuncAttributeMaxDynamicSharedMemorySize, SCORES_SMEM);
    cudaFuncSetAttribute(ctx_kernel,
                         cudaFuncAttributeMaxDynamicSharedMemorySize, CTX_SMEM);

    // 1) fused QKV projection
    {
        dim3 grid(QKVN / 128, M_ / 128);
        qkv_gemm_kernel<<<grid, 256>>>(x, Wqkv, bqkv);
    }
    // 2a) raw scores + mask
    {
        dim3 grid(S_ / 128, S_ / 128, B_ * H_);
        scores_kernel<<<grid, 256, SCORES_SMEM>>>(mask, att);
    }
    // 2b) row softmax in place
    {
        softmax_kernel<<<(B_ * H_ * S_) / 8, 256>>>(att);
    }
    // 2c) ctx = att @ V
    {
        dim3 grid(S_ / 128, B_ * H_);
        ctx_kernel<<<grid, 256, CTX_SMEM>>>(att);
    }
    // 3) output projection
    {
        dim3 grid(D_ / 128, M_ / 128);
        out_gemm_kernel<<<grid, 256>>>(Wo, bo, out);
    }
}

// round 9
// speedup vs baseline: 1.8588x; 1.0678x over previous
#include <cuda_runtime.h>
#include <cstdint>

// Problem constants
#define B_   4
#define S_   1024
#define D_   1024
#define H_   16
#define HD_  64
#define QKVN 3072
#define M_   (B_ * S_)

// Scratch (static device globals — allocation-free per harness rules)
__device__ float g_qkv[(size_t)M_ * QKVN];     // [b,s, h*192 + {q,k,v}*64]
__device__ float g_ctx[(size_t)M_ * D_];       // [b,s, h*64+d]
__device__ float2 g_part[(size_t)B_ * H_ * S_ * 8];  // per (bh,q,ktile): (max, expsum)

// ---------------------------------------------------------------------------
// helpers
// ---------------------------------------------------------------------------
__device__ __forceinline__ float to_tf32(float x) {
    uint32_t u;
    asm("cvt.rna.tf32.f32 %0, %1;" : "=r"(u) : "f"(x));
    return __uint_as_float(u);
}

__device__ __forceinline__ void mma_tf32(float* d, const uint32_t* a, const uint32_t* b) {
    asm volatile(
        "mma.sync.aligned.m16n8k8.row.col.f32.tf32.tf32.f32 "
        "{%0,%1,%2,%3}, {%4,%5,%6,%7}, {%8,%9}, {%0,%1,%2,%3};\n"
        : "+f"(d[0]), "+f"(d[1]), "+f"(d[2]), "+f"(d[3])
        : "r"(a[0]), "r"(a[1]), "r"(a[2]), "r"(a[3]), "r"(b[0]), "r"(b[1]));
}

// ---------------------------------------------------------------------------
// tf32 GEMM (proven form): 128x128 tile, BK=32, 8 warps (4M x 2N),
// warp tile 32x64, static smem, single buffer.  FROZEN since R3.
// ---------------------------------------------------------------------------
#define BK   32
#define ASTR 36
#define BSTR 136

__device__ __forceinline__ void gemm_tf32_body(
    const float* __restrict__ A, const float* __restrict__ Bm,
    const float* __restrict__ bias, float* __restrict__ C,
    int N, int K)
{
    __shared__ float As[128 * ASTR];
    __shared__ float Bs[BK * BSTR];

    const int tid  = threadIdx.x;
    const int lane = tid & 31;
    const int wid  = tid >> 5;
    const int wm   = (wid & 3) * 32;
    const int wn   = (wid >> 2) * 64;
    const int bx   = blockIdx.x * 128;
    const int by   = blockIdx.y * 128;

    const int g = lane >> 2;
    const int a = lane & 3;

    float acc[2][8][4];
#pragma unroll
    for (int i = 0; i < 2; i++)
#pragma unroll
        for (int j = 0; j < 8; j++)
#pragma unroll
            for (int v = 0; v < 4; v++) acc[i][j][v] = 0.f;

    const int arow0 = tid >> 3;
    const int acol  = (tid & 7) * 4;
    const int brow0 = tid >> 5;
    const int bcol  = (tid & 31) * 4;

    for (int k0 = 0; k0 < K; k0 += BK) {
        float4 av[4], bv[4];
#pragma unroll
        for (int i = 0; i < 4; i++)
            av[i] = *(const float4*)(A + (size_t)(by + arow0 + 32 * i) * K + k0 + acol);
#pragma unroll
        for (int i = 0; i < 4; i++)
            bv[i] = *(const float4*)(Bm + (size_t)(k0 + brow0 + 8 * i) * N + bx + bcol);

        __syncthreads();
#pragma unroll
        for (int i = 0; i < 4; i++) {
            float4 t = av[i];
            t.x = to_tf32(t.x); t.y = to_tf32(t.y); t.z = to_tf32(t.z); t.w = to_tf32(t.w);
            *(float4*)(As + (arow0 + 32 * i) * ASTR + acol) = t;
        }
#pragma unroll
        for (int i = 0; i < 4; i++) {
            float4 t = bv[i];
            t.x = to_tf32(t.x); t.y = to_tf32(t.y); t.z = to_tf32(t.z); t.w = to_tf32(t.w);
            *(float4*)(Bs + (brow0 + 8 * i) * BSTR + bcol) = t;
        }
        __syncthreads();

#pragma unroll
        for (int kk = 0; kk < BK; kk += 8) {
            uint32_t af[2][4], bf[8][2];
#pragma unroll
            for (int i = 0; i < 2; i++) {
                int r = wm + i * 16 + g;
                af[i][0] = __float_as_uint(As[(r)     * ASTR + kk + a]);
                af[i][1] = __float_as_uint(As[(r + 8) * ASTR + kk + a]);
                af[i][2] = __float_as_uint(As[(r)     * ASTR + kk + 4 + a]);
                af[i][3] = __float_as_uint(As[(r + 8) * ASTR + kk + 4 + a]);
            }
#pragma unroll
            for (int j = 0; j < 8; j++) {
                int n = wn + j * 8 + g;
                bf[j][0] = __float_as_uint(Bs[(kk + a)     * BSTR + n]);
                bf[j][1] = __float_as_uint(Bs[(kk + 4 + a) * BSTR + n]);
            }
#pragma unroll
            for (int i = 0; i < 2; i++)
#pragma unroll
                for (int j = 0; j < 8; j++)
                    mma_tf32(acc[i][j], af[i], bf[j]);
        }
    }

#pragma unroll
    for (int i = 0; i < 2; i++) {
        int row = by + wm + i * 16 + g;
#pragma unroll
        for (int j = 0; j < 8; j++) {
            int col = bx + wn + j * 8 + a * 2;
            float b0 = bias[col], b1 = bias[col + 1];
            *(float2*)(C + (size_t)row * N + col) =
                make_float2(acc[i][j][0] + b0, acc[i][j][1] + b1);
            *(float2*)(C + (size_t)(row + 8) * N + col) =
                make_float2(acc[i][j][2] + b0, acc[i][j][3] + b1);
        }
    }
}

__global__ __launch_bounds__(256) void qkv_gemm_kernel(
    const float* __restrict__ x, const float* __restrict__ W,
    const float* __restrict__ bias)
{
    gemm_tf32_body(x, W, bias, g_qkv, QKVN, D_);
}

__global__ __launch_bounds__(256) void out_gemm_kernel(
    const float* __restrict__ W, const float* __restrict__ bias,
    float* __restrict__ out)
{
    gemm_tf32_body(g_ctx, W, bias, out, D_, D_);
}

// ---------------------------------------------------------------------------
// scores kernel: att_raw = (Q*0.125) @ K^T + mask; also emits per-row
// per-tile softmax partials (max, sum exp(s-max)) into g_part.
// per block: 128q x 128k of one (b,h). 8 warps (4M x 2N), warp tile 32x64.
// ---------------------------------------------------------------------------
#define SC_STR 68
#define SCORES_SMEM ((128 * SC_STR * 2) * 4)

__global__ __launch_bounds__(256) void scores_kernel(
    const float* __restrict__ mask, float* __restrict__ att)
{
    extern __shared__ float sms[];
    float* Qs = sms;                 // [128][68]
    float* Ks = sms + 128 * SC_STR;  // [128][68]
    __shared__ float sm_part[128][2][2];   // [row][wn-half][max,sum]

    const int bh = blockIdx.z;
    const int b  = bh >> 4, h = bh & 15;
    const int qt = blockIdx.y * 128;
    const int kt = blockIdx.x * 128;
    const int tid = threadIdx.x;
    const int lane = tid & 31, w = tid >> 5;
    const int g = lane >> 2, a = lane & 3;
    const int wm = (w & 3) * 32, wn = (w >> 2) * 64;

    const float* qkv_b = g_qkv + (size_t)(b * S_) * QKVN + h * 192;

    // load Q & K tiles (tf32; Q pre-scaled)
    {
        int row = tid >> 4;            // 0..15 (+16*i)
        int c4  = (tid & 15) * 4;
#pragma unroll
        for (int i = 0; i < 8; i++) {
            float4 t = *(const float4*)(qkv_b + (size_t)(qt + row + 16 * i) * QKVN + c4);
            t.x = to_tf32(t.x * 0.125f); t.y = to_tf32(t.y * 0.125f);
            t.z = to_tf32(t.z * 0.125f); t.w = to_tf32(t.w * 0.125f);
            *(float4*)(Qs + (row + 16 * i) * SC_STR + c4) = t;
        }
#pragma unroll
        for (int i = 0; i < 8; i++) {
            float4 t = *(const float4*)(qkv_b + (size_t)(kt + row + 16 * i) * QKVN + 64 + c4);
            t.x = to_tf32(t.x); t.y = to_tf32(t.y); t.z = to_tf32(t.z); t.w = to_tf32(t.w);
            *(float4*)(Ks + (row + 16 * i) * SC_STR + c4) = t;
        }
    }
    __syncthreads();

    float acc[2][8][4];
#pragma unroll
    for (int i = 0; i < 2; i++)
#pragma unroll
        for (int j = 0; j < 8; j++)
#pragma unroll
            for (int v = 0; v < 4; v++) acc[i][j][v] = 0.f;

#pragma unroll
    for (int ks = 0; ks < 8; ks++) {
        int k0 = ks * 8;
        uint32_t af[2][4], bf[8][2];
#pragma unroll
        for (int i = 0; i < 2; i++) {
            int r = wm + i * 16 + g;
            af[i][0] = __float_as_uint(Qs[(r)     * SC_STR + k0 + a]);
            af[i][1] = __float_as_uint(Qs[(r + 8) * SC_STR + k0 + a]);
            af[i][2] = __float_as_uint(Qs[(r)     * SC_STR + k0 + 4 + a]);
            af[i][3] = __float_as_uint(Qs[(r + 8) * SC_STR + k0 + 4 + a]);
        }
#pragma unroll
        for (int j = 0; j < 8; j++) {
            int n = wn + j * 8 + g;
            bf[j][0] = __float_as_uint(Ks[n * SC_STR + k0 + a]);
            bf[j][1] = __float_as_uint(Ks[n * SC_STR + k0 + 4 + a]);
        }
#pragma unroll
        for (int i = 0; i < 2; i++)
#pragma unroll
            for (int j = 0; j < 8; j++)
                mma_tf32(acc[i][j], af[i], bf[j]);
    }

    // epilogue: + mask, write raw att, per-row tile (max, expsum) partials
    float* abase = att + ((size_t)(b * H_ + h) * S_ + qt) * S_ + kt;
    const float* mbase = mask + ((size_t)(b * S_) + qt) * S_ + kt;
#pragma unroll
    for (int i = 0; i < 2; i++) {
        int r0 = wm + i * 16 + g;
        float mx0 = -1e30f, mx1 = -1e30f;
#pragma unroll
        for (int j = 0; j < 8; j++) {
            int col = wn + j * 8 + a * 2;
            float2 m0 = *(const float2*)(mbase + (size_t)r0 * S_ + col);
            float2 m1 = *(const float2*)(mbase + (size_t)(r0 + 8) * S_ + col);
            acc[i][j][0] += m0.x; acc[i][j][1] += m0.y;
            acc[i][j][2] += m1.x; acc[i][j][3] += m1.y;
            *(float2*)(abase + (size_t)r0 * S_ + col) =
                make_float2(acc[i][j][0], acc[i][j][1]);
            *(float2*)(abase + (size_t)(r0 + 8) * S_ + col) =
                make_float2(acc[i][j][2], acc[i][j][3]);
            mx0 = fmaxf(mx0, fmaxf(acc[i][j][0], acc[i][j][1]));
            mx1 = fmaxf(mx1, fmaxf(acc[i][j][2], acc[i][j][3]));
        }
        mx0 = fmaxf(mx0, __shfl_xor_sync(~0u, mx0, 1));
        mx0 = fmaxf(mx0, __shfl_xor_sync(~0u, mx0, 2));
        mx1 = fmaxf(mx1, __shfl_xor_sync(~0u, mx1, 1));
        mx1 = fmaxf(mx1, __shfl_xor_sync(~0u, mx1, 2));
        float s0 = 0.f, s1 = 0.f;
#pragma unroll
        for (int j = 0; j < 8; j++) {
            s0 += __expf(acc[i][j][0] - mx0) + __expf(acc[i][j][1] - mx0);
            s1 += __expf(acc[i][j][2] - mx1) + __expf(acc[i][j][3] - mx1);
        }
        s0 += __shfl_xor_sync(~0u, s0, 1); s0 += __shfl_xor_sync(~0u, s0, 2);
        s1 += __shfl_xor_sync(~0u, s1, 1); s1 += __shfl_xor_sync(~0u, s1, 2);
        if (a == 0) {
            int half = wn >> 6;
            sm_part[r0][half][0]     = mx0; sm_part[r0][half][1]     = s0;
            sm_part[r0 + 8][half][0] = mx1; sm_part[r0 + 8][half][1] = s1;
        }
    }
    __syncthreads();
    if (tid < 128) {
        float m0 = sm_part[tid][0][0], s0 = sm_part[tid][0][1];
        float m1 = sm_part[tid][1][0], s1 = sm_part[tid][1][1];
        float M = fmaxf(m0, m1);
        float S = s0 * __expf(m0 - M) + s1 * __expf(m1 - M);
        g_part[((size_t)bh * S_ + qt + tid) * 8 + blockIdx.x] = make_float2(M, S);
    }
}

// ---------------------------------------------------------------------------
// ctx kernel: combines softmax partials -> exact row (M, 1/S); transforms
// raw scores p = exp(s-M)/S on the fly, writes normalized att, and computes
// g_ctx = P @ V.  per block: 128 rows x 64 dims of one (b,h); BK=64 chunks,
// double-buffered. 8 warps (4M x 2N), warp tile 32x32.
// ---------------------------------------------------------------------------
#define CT_ASTR 68
#define CT_VSTR 72
#define CT_AT   (128 * CT_ASTR)
#define CT_VT   (64 * CT_VSTR)
#define CTX_SMEM (2 * (CT_AT + CT_VT) * 4)

__global__ __launch_bounds__(256) void ctx_kernel(float* __restrict__ att)
{
    extern __shared__ float smc[];
    float* As = smc;                // [2][128][68]
    float* Vs = smc + 2 * CT_AT;    // [2][64][72]
    __shared__ float sm_M[128], sm_inv[128];

    const int bh = blockIdx.y;
    const int b  = bh >> 4, h = bh & 15;
    const int mt = blockIdx.x * 128;
    const int tid = threadIdx.x;
    const int lane = tid & 31, w = tid >> 5;
    const int g = lane >> 2, a = lane & 3;
    const int wm = (w & 3) * 32, wn = (w >> 2) * 32;

    float* abase = att + ((size_t)bh * S_ + mt) * S_;
    const float* vbase = g_qkv + (size_t)(b * S_) * QKVN + h * 192 + 128;

    const int lrow = tid >> 4;          // 0..15
    const int lc4  = (tid & 15) * 4;

    // combine the 8 per-tile partials into exact row (M, 1/S)
    if (tid < 128) {
        const float2* pp = g_part + ((size_t)bh * S_ + mt + tid) * 8;
        float2 t[8];
#pragma unroll
        for (int k = 0; k < 8; k++) t[k] = pp[k];
        float M = t[0].x;
#pragma unroll
        for (int k = 1; k < 8; k++) M = fmaxf(M, t[k].x);
        float S = 0.f;
#pragma unroll
        for (int k = 0; k < 8; k++) S += t[k].y * __expf(t[k].x - M);
        sm_M[tid] = M;
        sm_inv[tid] = 1.f / S;
    }
    __syncthreads();

    float rowM[8], rowInv[8];
#pragma unroll
    for (int i = 0; i < 8; i++) {
        rowM[i]   = sm_M[lrow + 16 * i];
        rowInv[i] = sm_inv[lrow + 16 * i];
    }

    float4 avr[8], bvr[4];

#define A_LDG(c)                                                               \
    {                                                                          \
        _Pragma("unroll")                                                      \
        for (int i = 0; i < 8; i++)                                            \
            avr[i] = *(const float4*)(abase + (size_t)(lrow + 16 * i) * S_ +   \
                                      (c) * 64 + lc4);                         \
    }
    // softmax transform + write normalized att + stage tf32 into smem
#define A_STS(buf, c)                                                          \
    {                                                                          \
        float* dst = As + (buf) * CT_AT;                                       \
        _Pragma("unroll")                                                      \
        for (int i = 0; i < 8; i++) {                                          \
            float4 t = avr[i];                                                 \
            t.x = __expf(t.x - rowM[i]) * rowInv[i];                           \
            t.y = __expf(t.y - rowM[i]) * rowInv[i];                           \
            t.z = __expf(t.z - rowM[i]) * rowInv[i];                           \
            t.w = __expf(t.w - rowM[i]) * rowInv[i];                           \
            *(float4*)(abase + (size_t)(lrow + 16 * i) * S_ + (c) * 64 + lc4) = t; \
            t.x = to_tf32(t.x); t.y = to_tf32(t.y);                            \
            t.z = to_tf32(t.z); t.w = to_tf32(t.w);                            \
            *(float4*)(dst + (lrow + 16 * i) * CT_ASTR + lc4) = t;             \
        }                                                                      \
    }
#define V_LDG(c)                                                               \
    {                                                                          \
        _Pragma("unroll")                                                      \
        for (int i = 0; i < 4; i++)                                            \
            bvr[i] = *(const float4*)(vbase +                                  \
                (size_t)((c) * 64 + lrow + 16 * i) * QKVN + lc4);              \
    }
#define V_STS(buf)                                                             \
    {                                                                          \
        float* dst = Vs + (buf) * CT_VT;                                       \
        _Pragma("unroll")                                                      \
        for (int i = 0; i < 4; i++) {                                          \
            float4 t = bvr[i];                                                 \
            t.x = to_tf32(t.x); t.y = to_tf32(t.y);                            \
            t.z = to_tf32(t.z); t.w = to_tf32(t.w);                            \
            *(float4*)(dst + (lrow + 16 * i) * CT_VSTR + lc4) = t;             \
        }                                                                      \
    }

    float acc[2][4][4];
#pragma unroll
    for (int i = 0; i < 2; i++)
#pragma unroll
        for (int j = 0; j < 4; j++)
#pragma unroll
            for (int v = 0; v < 4; v++) acc[i][j][v] = 0.f;

    const int nk = S_ / 64;   // 16 chunks
    A_LDG(0); A_STS(0, 0);
    V_LDG(0); V_STS(0);
    A_LDG(1); V_LDG(1);
    __syncthreads();

    for (int c = 0; c < nk; c++) {
        const float* Ab_ = As + (c & 1) * CT_AT;
        const float* Vb_ = Vs + (c & 1) * CT_VT;
        if (c + 1 < nk) { A_STS((c + 1) & 1, c + 1); V_STS((c + 1) & 1); }
        if (c + 2 < nk) { A_LDG(c + 2); V_LDG(c + 2); }

#pragma unroll
        for (int kk = 0; kk < 64; kk += 8) {
            uint32_t af[2][4], bf[4][2];
#pragma unroll
            for (int i = 0; i < 2; i++) {
                int r = wm + i * 16 + g;
                af[i][0] = __float_as_uint(Ab_[(r)     * CT_ASTR + kk + a]);
                af[i][1] = __float_as_uint(Ab_[(r + 8) * CT_ASTR + kk + a]);
                af[i][2] = __float_as_uint(Ab_[(r)     * CT_ASTR + kk + 4 + a]);
                af[i][3] = __float_as_uint(Ab_[(r + 8) * CT_ASTR + kk + 4 + a]);
            }
#pragma unroll
            for (int j = 0; j < 4; j++) {
                int n = wn + j * 8 + g;
                bf[j][0] = __float_as_uint(Vb_[(kk + a)     * CT_VSTR + n]);
                bf[j][1] = __float_as_uint(Vb_[(kk + 4 + a) * CT_VSTR + n]);
            }
#pragma unroll
            for (int i = 0; i < 2; i++)
#pragma unroll
                for (int j = 0; j < 4; j++)
                    mma_tf32(acc[i][j], af[i], bf[j]);
        }
        __syncthreads();
    }
#undef A_LDG
#undef A_STS
#undef V_LDG
#undef V_STS

#pragma unroll
    for (int i = 0; i < 2; i++) {
        int row = mt + wm + i * 16 + g;
#pragma unroll
        for (int j = 0; j < 4; j++) {
            int col = wn + j * 8 + a * 2;
            *(float2*)(g_ctx + (size_t)(b * S_ + row) * D_ + h * HD_ + col) =
                make_float2(acc[i][j][0], acc[i][j][1]);
            *(float2*)(g_ctx + (size_t)(b * S_ + row + 8) * D_ + h * HD_ + col) =
                make_float2(acc[i][j][2], acc[i][j][3]);
        }
    }
}

// ---------------------------------------------------------------------------
extern "C" void kernel_launch(void* const* d_in, const int* in_sizes, int n_in,
                              void* d_out, int out_size)
{
    const float* x    = (const float*)d_in[0];
    const float* mask = (const float*)d_in[1];
    const float* Wqkv = (const float*)d_in[2];
    const float* bqkv = (const float*)d_in[3];
    const float* Wo   = (const float*)d_in[4];
    const float* bo   = (const float*)d_in[5];

    float* out = (float*)d_out;                       // [B,S,D]
    float* att = out + (size_t)B_ * S_ * D_;          // [B,H,S,S]

    cudaFuncSetAttribute(scores_kernel,
                         cudaFuncAttributeMaxDynamicSharedMemorySize, SCORES_SMEM);
    cudaFuncSetAttribute(ctx_kernel,
                         cudaFuncAttributeMaxDynamicSharedMemorySize, CTX_SMEM);

    // 1) fused QKV projection
    {
        dim3 grid(QKVN / 128, M_ / 128);
        qkv_gemm_kernel<<<grid, 256>>>(x, Wqkv, bqkv);
    }
    // 2a) raw scores + mask + softmax partials
    {
        dim3 grid(S_ / 128, S_ / 128, B_ * H_);
        scores_kernel<<<grid, 256, SCORES_SMEM>>>(mask, att);
    }
    // 2b) ctx = softmax(att) @ V, normalized att written in-flight
    {
        dim3 grid(S_ / 128, B_ * H_);
        ctx_kernel<<<grid, 256, CTX_SMEM>>>(att);
    }
    // 3) output projection
    {
        dim3 grid(D_ / 128, M_ / 128);
        out_gemm_kernel<<<grid, 256>>>(Wo, bo, out);
    }
}